// round 14
// baseline (speedup 1.0000x reference)
#include <cuda_runtime.h>
#include <cuda_fp16.h>
#include <math.h>
#include <stdint.h>

// Problem dims
#define BATCH 32
#define PTOK  256
#define DIM   2048
#define HID   8192
#define NVIEW 3
#define ROWS  (BATCH * PTOK)   // 8192

// ---------------------------------------------------------------------------
// Device scratch
// ---------------------------------------------------------------------------
__device__ int g_idx[BATCH];
__device__ int g_morder[ROWS / 128];

__device__ __half g_xah[(size_t)ROWS * DIM];
__device__ __half g_xal[(size_t)ROWS * DIM];
__device__ __half g_hh [(size_t)ROWS * HID];
__device__ __half g_hl [(size_t)ROWS * HID];
__device__ __half g_w1h[(size_t)NVIEW * HID * DIM];  // [v][n][k]
__device__ __half g_w1l[(size_t)NVIEW * HID * DIM];
__device__ __half g_w2h[(size_t)NVIEW * DIM * HID];
__device__ __half g_w2l[(size_t)NVIEW * DIM * HID];

// ---------------------------------------------------------------------------
// PTX helpers (base sm_103-safe)
// ---------------------------------------------------------------------------
__device__ __forceinline__ uint32_t smem_u32(const void* p) {
    uint32_t a;
    asm("{ .reg .u64 t; cvta.to.shared.u64 t, %1; cvt.u32.u64 %0, t; }"
        : "=r"(a) : "l"(p));
    return a;
}

__device__ __forceinline__ void cp16(uint32_t dst, const void* src) {
    asm volatile("cp.async.cg.shared.global [%0], [%1], 16;" :: "r"(dst), "l"(src));
}
#define CP_COMMIT() asm volatile("cp.async.commit_group;" ::: "memory")
#define CP_WAIT(n)  asm volatile("cp.async.wait_group %0;" :: "n"(n) : "memory")

__device__ __forceinline__ void ldm4(uint32_t* r, uint32_t a) {
    asm volatile("ldmatrix.sync.aligned.m8n8.x4.shared.b16 {%0,%1,%2,%3}, [%4];"
        : "=r"(r[0]), "=r"(r[1]), "=r"(r[2]), "=r"(r[3]) : "r"(a));
}

// fp16 inputs, fp32 accumulator (main term)
__device__ __forceinline__ void mma_f32(float* c, const uint32_t* a,
                                        uint32_t b0, uint32_t b1) {
    asm volatile(
        "mma.sync.aligned.m16n8k16.row.col.f32.f16.f16.f32 "
        "{%0,%1,%2,%3}, {%4,%5,%6,%7}, {%8,%9}, {%0,%1,%2,%3};"
        : "+f"(c[0]), "+f"(c[1]), "+f"(c[2]), "+f"(c[3])
        : "r"(a[0]), "r"(a[1]), "r"(a[2]), "r"(a[3]), "r"(b0), "r"(b1));
}

// fp16 inputs, fp16 accumulator (cross terms — small magnitude)
__device__ __forceinline__ void mma_f16(uint32_t* c, const uint32_t* a,
                                        uint32_t b0, uint32_t b1) {
    asm volatile(
        "mma.sync.aligned.m16n8k16.row.col.f16.f16.f16.f16 "
        "{%0,%1}, {%2,%3,%4,%5}, {%6,%7}, {%0,%1};"
        : "+r"(c[0]), "+r"(c[1])
        : "r"(a[0]), "r"(a[1]), "r"(a[2]), "r"(a[3]), "r"(b0), "r"(b1));
}

// ---------------------------------------------------------------------------
// decode idx + view-sorted M-tile order (128-row tiles: 2 per sample)
// ---------------------------------------------------------------------------
__global__ void decode_idx_kernel(const int* __restrict__ p) {
    bool is64 = true;
    for (int b = 0; b < BATCH; b++) {
        int lo = p[2 * b], hi = p[2 * b + 1];
        if (!(lo >= 0 && lo < NVIEW && hi == 0)) { is64 = false; break; }
    }
    for (int b = 0; b < BATCH; b++) g_idx[b] = is64 ? p[2 * b] : p[b];
    int c = 0;
    for (int v = 0; v < NVIEW; v++)
        for (int s = 0; s < BATCH; s++)
            if (g_idx[s] == v) { g_morder[c++] = 2 * s; g_morder[c++] = 2 * s + 1; }
}

// ---------------------------------------------------------------------------
// LayerNorm -> fp16 hi/lo planes
// ---------------------------------------------------------------------------
__global__ void __launch_bounds__(256) ln_kernel(
    const float* __restrict__ x,
    const float* __restrict__ gamma,
    const float* __restrict__ beta)
{
    const int row = blockIdx.x;
    const int view = g_idx[row >> 8];
    const float* xr = x + (size_t)row * DIM;
    const int tid = threadIdx.x;

    float4 v0 = *(const float4*)(xr + tid * 4);
    float4 v1 = *(const float4*)(xr + 1024 + tid * 4);

    float s  = v0.x + v0.y + v0.z + v0.w + v1.x + v1.y + v1.z + v1.w;
    float ss = v0.x*v0.x + v0.y*v0.y + v0.z*v0.z + v0.w*v0.w
             + v1.x*v1.x + v1.y*v1.y + v1.z*v1.z + v1.w*v1.w;
    #pragma unroll
    for (int off = 16; off > 0; off >>= 1) {
        s  += __shfl_xor_sync(0xffffffffu, s,  off);
        ss += __shfl_xor_sync(0xffffffffu, ss, off);
    }
    __shared__ float rs[8], rss[8];
    int wid = tid >> 5, lane = tid & 31;
    if (lane == 0) { rs[wid] = s; rss[wid] = ss; }
    __syncthreads();
    if (wid == 0) {
        float a = (lane < 8) ? rs[lane] : 0.f;
        float b = (lane < 8) ? rss[lane] : 0.f;
        #pragma unroll
        for (int off = 4; off > 0; off >>= 1) {
            a += __shfl_xor_sync(0xffffffffu, a, off);
            b += __shfl_xor_sync(0xffffffffu, b, off);
        }
        if (lane == 0) { rs[0] = a; rss[0] = b; }
    }
    __syncthreads();
    const float mean = rs[0] * (1.0f / DIM);
    const float var  = rss[0] * (1.0f / DIM) - mean * mean;
    const float inv  = rsqrtf(var + 1e-5f);

    const float* g = gamma + (size_t)view * DIM;
    const float* b = beta  + (size_t)view * DIM;
    size_t base = (size_t)row * DIM;

    float v[8];
    v[0]=v0.x; v[1]=v0.y; v[2]=v0.z; v[3]=v0.w; v[4]=v1.x; v[5]=v1.y; v[6]=v1.z; v[7]=v1.w;
    #pragma unroll
    for (int j = 0; j < 8; j++) {
        int c = (j < 4) ? (tid * 4 + j) : (1024 + tid * 4 + (j - 4));
        float o = (v[j] - mean) * inv * g[c] + b[c];
        __half hi = __float2half_rn(o);
        __half lo = __float2half_rn(o - __half2float(hi));
        g_xah[base + c] = hi;
        g_xal[base + c] = lo;
    }
}

// ---------------------------------------------------------------------------
// Fused weight transpose + fp16 split (vectorized): 32k x 64n tiles.
// blockIdx.y in [0,6): y<3 -> W1 view y ; y>=3 -> W2 view y-3
// ---------------------------------------------------------------------------
__global__ void __launch_bounds__(256) wt_all_kernel(
    const float* __restrict__ W1, const float* __restrict__ W2)
{
    __shared__ float t[32][65];
    const int yy = blockIdx.y;
    const bool isW1 = (yy < 3);
    const int v = isW1 ? yy : (yy - 3);
    const int K = isW1 ? DIM : HID;
    const int N = isW1 ? HID : DIM;
    const float* W = isW1 ? W1 : W2;
    __half* oh = isW1 ? g_w1h : g_w2h;
    __half* ol = isW1 ? g_w1l : g_w2l;

    const int nblk = N / 64;
    const int kb = blockIdx.x / nblk;
    const int nb = blockIdx.x % nblk;
    const int n0 = nb * 64, k0 = kb * 32;
    const int tid = threadIdx.x;

    // load 32 k-rows x 64 n-cols, float4 coalesced
    #pragma unroll
    for (int i = 0; i < 2; i++) {
        int cid = i * 256 + tid;             // 512 float4 = 32 rows x 16
        int row = cid >> 4, c4 = cid & 15;
        float4 val = *(const float4*)(W + ((size_t)v * K + k0 + row) * N + n0 + c4 * 4);
        t[row][c4 * 4 + 0] = val.x;
        t[row][c4 * 4 + 1] = val.y;
        t[row][c4 * 4 + 2] = val.z;
        t[row][c4 * 4 + 3] = val.w;
    }
    __syncthreads();

    // store transposed: each thread -> one (n, 8-k chunk), uint4 per plane
    const int n = tid >> 2;                  // 0..63
    const int kq = (tid & 3) * 8;            // 0,8,16,24
    __half hs[8], ls[8];
    #pragma unroll
    for (int i = 0; i < 8; i++) {
        float val = t[kq + i][n];
        __half hi = __float2half_rn(val);
        hs[i] = hi;
        ls[i] = __float2half_rn(val - __half2float(hi));
    }
    size_t o = ((size_t)v * N + n0 + n) * K + k0 + kq;
    *(uint4*)(oh + o) = *(const uint4*)hs;
    *(uint4*)(ol + o) = *(const uint4*)ls;
}

// ---------------------------------------------------------------------------
// Warp-MMA GEMM: D[128x128] = A[128xK] @ B[128xK]^T  (fp16 hi/lo, 3 terms)
// main -> fp32 acc ; cross terms -> fp16 acc.
// 256 threads = 8 warps (4M x 2N), warp tile 32x64. 2 CTAs/SM.
// K-chunk 32, 2-stage cp.async double buffer.
// MMA order per j16: group2(AlBh) -> group1(AhBh f32) -> group3(AhBl),
// widening every accX RAW chain to 8 MMAs.
// ---------------------------------------------------------------------------
#define KC     32
#define RSTR   80
#define A_PL   (128 * RSTR)             // 10240
#define B_PL   (128 * RSTR)             // 10240
#define STG    (2 * A_PL + 2 * B_PL)    // 40960 per stage
#define SMEM_DYN (2 * STG)              // 81920 per CTA (x2 CTAs = 164KB/SM)

template<int KTOT, int NTOT, bool GELU>
__global__ void __launch_bounds__(256, 2) gemm_mma(
    const __half* __restrict__ Ah, const __half* __restrict__ Al,
    const __half* __restrict__ Bh, const __half* __restrict__ Bl,
    const float* __restrict__ bias,
    const float* __restrict__ xres, float* __restrict__ outp,
    __half* __restrict__ outH, __half* __restrict__ outL)
{
    constexpr int NS = KTOT / KC;
    extern __shared__ char smem[];
    const uint32_t sbase = smem_u32(smem);
    const int tid = threadIdx.x;
    const int lane = tid & 31;
    const int wrp = tid >> 5;
    const int wm = wrp & 3;          // M warp (32 rows)
    const int wn = wrp >> 2;         // N warp (64 cols), 0..1

    // block mapping: groups of 8 N-tiles x all 64 view-sorted M-tiles
    const int bx = blockIdx.x;
    const int g = bx >> 9, r = bx & 511;
    const int mb = g_morder[r >> 3];
    const int nb = (g << 3) | (r & 7);
    const int view = g_idx[mb >> 1];
    const int grow = mb * 128;
    const size_t arow0 = (size_t)grow;
    const size_t brow0 = (size_t)view * NTOT + (size_t)nb * 128;
    const int gcol = nb * 128;

    const char* pAh = (const char*)Ah;
    const char* pAl = (const char*)Al;
    const char* pBh = (const char*)Bh;
    const char* pBl = (const char*)Bl;

    auto load_stage = [&](int s) {
        const int k0 = s * KC;
        const uint32_t stb = sbase + (s & 1) * STG;
        #pragma unroll
        for (int i = 0; i < 2; i++) {
            int cid = i * 256 + tid;              // 512 = 128 rows x 4 chunks
            int row = cid >> 2, c = cid & 3;
            uint32_t so = stb + row * RSTR + c * 16;
            size_t go = ((size_t)(arow0 + row) * KTOT + k0 + c * 8) * 2;
            cp16(so, pAh + go);
            cp16(so + A_PL, pAl + go);
        }
        #pragma unroll
        for (int i = 0; i < 2; i++) {
            int cid = i * 256 + tid;
            int row = cid >> 2, c = cid & 3;
            uint32_t so = stb + 2 * A_PL + row * RSTR + c * 16;
            size_t go = ((size_t)(brow0 + row) * KTOT + k0 + c * 8) * 2;
            cp16(so, pBh + go);
            cp16(so + B_PL, pBl + go);
        }
        CP_COMMIT();
    };

    const int lrow = (lane & 7) | (((lane >> 3) & 1) << 3);
    const int lhalf = lane >> 4;

    float    acc [2][8][4];
    uint32_t accX[2][8][2];
    #pragma unroll
    for (int i = 0; i < 2; i++)
        #pragma unroll
        for (int j = 0; j < 8; j++) {
            #pragma unroll
            for (int q = 0; q < 4; q++) acc[i][j][q] = 0.f;
            accX[i][j][0] = 0u; accX[i][j][1] = 0u;
        }

    load_stage(0);

    for (int s = 0; s < NS; s++) {
        CP_WAIT(0);
        __syncthreads();
        if (s + 1 < NS) load_stage(s + 1);

        const uint32_t stb = sbase + (s & 1) * STG;
        uint32_t aA = stb + (wm * 32 + lrow) * RSTR + lhalf * 16;
        uint32_t aB0 = stb + 2 * A_PL + (wn * 64 + lrow) * RSTR + lhalf * 16;

        #pragma unroll
        for (int kk = 0; kk < 2; kk++) {
            uint32_t ah[2][4], al[2][4];
            ldm4(ah[0], aA);
            ldm4(ah[1], aA + 16 * RSTR);
            ldm4(al[0], aA + A_PL);
            ldm4(al[1], aA + A_PL + 16 * RSTR);
            aA += 32;

            uint32_t aB = aB0;
            #pragma unroll
            for (int j16 = 0; j16 < 4; j16++) {
                uint32_t th[4], tl[4];
                ldm4(th, aB);
                ldm4(tl, aB + B_PL);
                aB += 16 * RSTR;

                const int j0 = 2 * j16, j1 = j0 + 1;
                // group 2: A-lo x B-hi (fp16 acc), 4 independent
                mma_f16(accX[0][j0], al[0], th[0], th[2]);
                mma_f16(accX[1][j0], al[1], th[0], th[2]);
                mma_f16(accX[0][j1], al[0], th[1], th[3]);
                mma_f16(accX[1][j1], al[1], th[1], th[3]);
                // group 1: main term (fp32 acc), 4 independent — separates
                // group2/group3 accX RAW chains by 4 extra MMAs
                mma_f32(acc[0][j0], ah[0], th[0], th[2]);
                mma_f32(acc[1][j0], ah[1], th[0], th[2]);
                mma_f32(acc[0][j1], ah[0], th[1], th[3]);
                mma_f32(acc[1][j1], ah[1], th[1], th[3]);
                // group 3: A-hi x B-lo (fp16 acc), 4 independent
                mma_f16(accX[0][j0], ah[0], tl[0], tl[2]);
                mma_f16(accX[1][j0], ah[1], tl[0], tl[2]);
                mma_f16(accX[0][j1], ah[0], tl[1], tl[3]);
                mma_f16(accX[1][j1], ah[1], tl[1], tl[3]);
            }
            aB0 += 32;
        }
    }

    // ---- epilogue ----
    const float* bias_v = bias + (size_t)view * NTOT;
    const int g4 = lane >> 2, t4 = lane & 3;

    #pragma unroll
    for (int i = 0; i < 2; i++) {
        #pragma unroll
        for (int j = 0; j < 8; j++) {
            const int row0 = grow + wm * 32 + i * 16 + g4;
            const int col  = gcol + wn * 64 + j * 8 + t4 * 2;
            const float b0 = __ldg(bias_v + col);
            const float b1 = __ldg(bias_v + col + 1);
            #pragma unroll
            for (int h = 0; h < 2; h++) {
                const int rw = row0 + h * 8;
                float2 xc = __half22float2(
                    *reinterpret_cast<const __half2*>(&accX[i][j][h]));
                float v0 = acc[i][j][h * 2 + 0] + xc.x + b0;
                float v1 = acc[i][j][h * 2 + 1] + xc.y + b1;
                const size_t go = (size_t)rw * NTOT + col;
                if (GELU) {
                    v0 = 0.5f * v0 * (1.0f + erff(v0 * 0.70710678118654752f));
                    v1 = 0.5f * v1 * (1.0f + erff(v1 * 0.70710678118654752f));
                    __half h0 = __float2half_rn(v0);
                    __half h1 = __float2half_rn(v1);
                    __half l0 = __float2half_rn(v0 - __half2float(h0));
                    __half l1 = __float2half_rn(v1 - __half2float(h1));
                    *(__half2*)(outH + go) = __halves2half2(h0, h1);
                    *(__half2*)(outL + go) = __halves2half2(l0, l1);
                } else {
                    float2 xv = *(const float2*)(xres + go);
                    float2 o;
                    o.x = xv.x + v0;
                    o.y = xv.y + v1;
                    *(float2*)(outp + go) = o;
                }
            }
        }
    }
}

// ---------------------------------------------------------------------------
// Launch
// ---------------------------------------------------------------------------
extern "C" void kernel_launch(void* const* d_in, const int* in_sizes, int n_in,
                              void* d_out, int out_size) {
    const float* x     = (const float*)d_in[0];
    const int*   idx   = (const int*)  d_in[1];
    const float* gamma = (const float*)d_in[2];
    const float* beta  = (const float*)d_in[3];
    const float* W1    = (const float*)d_in[4];
    const float* b1    = (const float*)d_in[5];
    const float* W2    = (const float*)d_in[6];
    const float* b2    = (const float*)d_in[7];
    float* out = (float*)d_out;

    void *p_xah, *p_xal, *p_hh, *p_hl, *p_w1h, *p_w1l, *p_w2h, *p_w2l;
    cudaGetSymbolAddress(&p_xah, g_xah);
    cudaGetSymbolAddress(&p_xal, g_xal);
    cudaGetSymbolAddress(&p_hh,  g_hh);
    cudaGetSymbolAddress(&p_hl,  g_hl);
    cudaGetSymbolAddress(&p_w1h, g_w1h);
    cudaGetSymbolAddress(&p_w1l, g_w1l);
    cudaGetSymbolAddress(&p_w2h, g_w2h);
    cudaGetSymbolAddress(&p_w2l, g_w2l);

    cudaFuncSetAttribute(gemm_mma<DIM, HID, true>,
                         cudaFuncAttributeMaxDynamicSharedMemorySize, SMEM_DYN);
    cudaFuncSetAttribute(gemm_mma<HID, DIM, false>,
                         cudaFuncAttributeMaxDynamicSharedMemorySize, SMEM_DYN);

    decode_idx_kernel<<<1, 1>>>(idx);
    ln_kernel<<<ROWS, 256>>>(x, gamma, beta);
    // W1: (K=2048/32)*(N=8192/64)=8192 blocks; W2: (8192/32)*(2048/64)=8192
    wt_all_kernel<<<dim3(8192, 6), 256>>>(W1, W2);

    // GEMM1: h = GELU(xn @ W1 + b1)   [8192x2048]x[2048x8192]
    gemm_mma<DIM, HID, true><<<(ROWS / 128) * (HID / 128), 256, SMEM_DYN>>>(
        (const __half*)p_xah, (const __half*)p_xal,
        (const __half*)p_w1h, (const __half*)p_w1l,
        b1, nullptr, nullptr,
        (__half*)p_hh, (__half*)p_hl);

    // GEMM2: out = x + h @ W2 + b2    [8192x8192]x[8192x2048]
    gemm_mma<HID, DIM, false><<<(ROWS / 128) * (DIM / 128), 256, SMEM_DYN>>>(
        (const __half*)p_hh, (const __half*)p_hl,
        (const __half*)p_w2h, (const __half*)p_w2l,
        b2, x, out, nullptr, nullptr);
}

// round 15
// speedup vs baseline: 1.3099x; 1.3099x over previous
#include <cuda_runtime.h>
#include <cuda_fp16.h>
#include <math.h>
#include <stdint.h>

// Problem dims
#define BATCH 32
#define PTOK  256
#define DIM   2048
#define HID   8192
#define NVIEW 3
#define ROWS  (BATCH * PTOK)   // 8192

// ---------------------------------------------------------------------------
// Device scratch
// ---------------------------------------------------------------------------
__device__ int g_idx[BATCH];
__device__ int g_morder[ROWS / 128];

__device__ __half g_xah[(size_t)ROWS * DIM];
__device__ __half g_xal[(size_t)ROWS * DIM];
__device__ __half g_hh [(size_t)ROWS * HID];
__device__ __half g_hl [(size_t)ROWS * HID];
__device__ __half g_w1h[(size_t)NVIEW * HID * DIM];  // [v][n][k], hi plane only
__device__ __half g_w2h[(size_t)NVIEW * DIM * HID];

// ---------------------------------------------------------------------------
// PTX helpers (base sm_103-safe)
// ---------------------------------------------------------------------------
__device__ __forceinline__ uint32_t smem_u32(const void* p) {
    uint32_t a;
    asm("{ .reg .u64 t; cvta.to.shared.u64 t, %1; cvt.u32.u64 %0, t; }"
        : "=r"(a) : "l"(p));
    return a;
}

__device__ __forceinline__ void cp16(uint32_t dst, const void* src) {
    asm volatile("cp.async.cg.shared.global [%0], [%1], 16;" :: "r"(dst), "l"(src));
}
#define CP_COMMIT() asm volatile("cp.async.commit_group;" ::: "memory")
#define CP_WAIT(n)  asm volatile("cp.async.wait_group %0;" :: "n"(n) : "memory")

__device__ __forceinline__ void ldm4(uint32_t* r, uint32_t a) {
    asm volatile("ldmatrix.sync.aligned.m8n8.x4.shared.b16 {%0,%1,%2,%3}, [%4];"
        : "=r"(r[0]), "=r"(r[1]), "=r"(r[2]), "=r"(r[3]) : "r"(a));
}

// fp16 inputs, fp32 accumulator (main term)
__device__ __forceinline__ void mma_f32(float* c, const uint32_t* a,
                                        uint32_t b0, uint32_t b1) {
    asm volatile(
        "mma.sync.aligned.m16n8k16.row.col.f32.f16.f16.f32 "
        "{%0,%1,%2,%3}, {%4,%5,%6,%7}, {%8,%9}, {%0,%1,%2,%3};"
        : "+f"(c[0]), "+f"(c[1]), "+f"(c[2]), "+f"(c[3])
        : "r"(a[0]), "r"(a[1]), "r"(a[2]), "r"(a[3]), "r"(b0), "r"(b1));
}

// fp16 inputs, fp16 accumulator (cross term — small magnitude)
__device__ __forceinline__ void mma_f16(uint32_t* c, const uint32_t* a,
                                        uint32_t b0, uint32_t b1) {
    asm volatile(
        "mma.sync.aligned.m16n8k16.row.col.f16.f16.f16.f16 "
        "{%0,%1}, {%2,%3,%4,%5}, {%6,%7}, {%0,%1};"
        : "+r"(c[0]), "+r"(c[1])
        : "r"(a[0]), "r"(a[1]), "r"(a[2]), "r"(a[3]), "r"(b0), "r"(b1));
}

// ---------------------------------------------------------------------------
// decode idx + view-sorted M-tile order (128-row tiles: 2 per sample)
// ---------------------------------------------------------------------------
__global__ void decode_idx_kernel(const int* __restrict__ p) {
    bool is64 = true;
    for (int b = 0; b < BATCH; b++) {
        int lo = p[2 * b], hi = p[2 * b + 1];
        if (!(lo >= 0 && lo < NVIEW && hi == 0)) { is64 = false; break; }
    }
    for (int b = 0; b < BATCH; b++) g_idx[b] = is64 ? p[2 * b] : p[b];
    int c = 0;
    for (int v = 0; v < NVIEW; v++)
        for (int s = 0; s < BATCH; s++)
            if (g_idx[s] == v) { g_morder[c++] = 2 * s; g_morder[c++] = 2 * s + 1; }
}

// ---------------------------------------------------------------------------
// LayerNorm -> fp16 hi/lo planes
// ---------------------------------------------------------------------------
__global__ void __launch_bounds__(256) ln_kernel(
    const float* __restrict__ x,
    const float* __restrict__ gamma,
    const float* __restrict__ beta)
{
    const int row = blockIdx.x;
    const int view = g_idx[row >> 8];
    const float* xr = x + (size_t)row * DIM;
    const int tid = threadIdx.x;

    float4 v0 = *(const float4*)(xr + tid * 4);
    float4 v1 = *(const float4*)(xr + 1024 + tid * 4);

    float s  = v0.x + v0.y + v0.z + v0.w + v1.x + v1.y + v1.z + v1.w;
    float ss = v0.x*v0.x + v0.y*v0.y + v0.z*v0.z + v0.w*v0.w
             + v1.x*v1.x + v1.y*v1.y + v1.z*v1.z + v1.w*v1.w;
    #pragma unroll
    for (int off = 16; off > 0; off >>= 1) {
        s  += __shfl_xor_sync(0xffffffffu, s,  off);
        ss += __shfl_xor_sync(0xffffffffu, ss, off);
    }
    __shared__ float rs[8], rss[8];
    int wid = tid >> 5, lane = tid & 31;
    if (lane == 0) { rs[wid] = s; rss[wid] = ss; }
    __syncthreads();
    if (wid == 0) {
        float a = (lane < 8) ? rs[lane] : 0.f;
        float b = (lane < 8) ? rss[lane] : 0.f;
        #pragma unroll
        for (int off = 4; off > 0; off >>= 1) {
            a += __shfl_xor_sync(0xffffffffu, a, off);
            b += __shfl_xor_sync(0xffffffffu, b, off);
        }
        if (lane == 0) { rs[0] = a; rss[0] = b; }
    }
    __syncthreads();
    const float mean = rs[0] * (1.0f / DIM);
    const float var  = rss[0] * (1.0f / DIM) - mean * mean;
    const float inv  = rsqrtf(var + 1e-5f);

    const float* g = gamma + (size_t)view * DIM;
    const float* b = beta  + (size_t)view * DIM;
    size_t base = (size_t)row * DIM;

    float v[8];
    v[0]=v0.x; v[1]=v0.y; v[2]=v0.z; v[3]=v0.w; v[4]=v1.x; v[5]=v1.y; v[6]=v1.z; v[7]=v1.w;
    #pragma unroll
    for (int j = 0; j < 8; j++) {
        int c = (j < 4) ? (tid * 4 + j) : (1024 + tid * 4 + (j - 4));
        float o = (v[j] - mean) * inv * g[c] + b[c];
        __half hi = __float2half_rn(o);
        __half lo = __float2half_rn(o - __half2float(hi));
        g_xah[base + c] = hi;
        g_xal[base + c] = lo;
    }
}

// ---------------------------------------------------------------------------
// Fused weight transpose + fp16 (hi plane only): 32k x 64n tiles.
// blockIdx.y in [0,6): y<3 -> W1 view y ; y>=3 -> W2 view y-3
// ---------------------------------------------------------------------------
__global__ void __launch_bounds__(256) wt_all_kernel(
    const float* __restrict__ W1, const float* __restrict__ W2)
{
    __shared__ float t[32][65];
    const int yy = blockIdx.y;
    const bool isW1 = (yy < 3);
    const int v = isW1 ? yy : (yy - 3);
    const int K = isW1 ? DIM : HID;
    const int N = isW1 ? HID : DIM;
    const float* W = isW1 ? W1 : W2;
    __half* oh = isW1 ? g_w1h : g_w2h;

    const int nblk = N / 64;
    const int kb = blockIdx.x / nblk;
    const int nb = blockIdx.x % nblk;
    const int n0 = nb * 64, k0 = kb * 32;
    const int tid = threadIdx.x;

    #pragma unroll
    for (int i = 0; i < 2; i++) {
        int cid = i * 256 + tid;             // 512 float4 = 32 rows x 16
        int row = cid >> 4, c4 = cid & 15;
        float4 val = *(const float4*)(W + ((size_t)v * K + k0 + row) * N + n0 + c4 * 4);
        t[row][c4 * 4 + 0] = val.x;
        t[row][c4 * 4 + 1] = val.y;
        t[row][c4 * 4 + 2] = val.z;
        t[row][c4 * 4 + 3] = val.w;
    }
    __syncthreads();

    const int n = tid >> 2;                  // 0..63
    const int kq = (tid & 3) * 8;            // 0,8,16,24
    __half hs[8];
    #pragma unroll
    for (int i = 0; i < 8; i++)
        hs[i] = __float2half_rn(t[kq + i][n]);
    size_t o = ((size_t)v * N + n0 + n) * K + k0 + kq;
    *(uint4*)(oh + o) = *(const uint4*)hs;
}

// ---------------------------------------------------------------------------
// Warp-MMA GEMM: D[128x128] = A[128xK] @ B[128xK]^T, 2-term fp16:
//   (Ah + Al) @ Bh ;  main (Ah·Bh) -> fp32 acc, cross (Al·Bh) -> fp16 acc.
// 256 threads = 8 warps (4M x 2N), warp tile 32x64. 2 CTAs/SM.
// K-chunk 32, 2-stage cp.async double buffer.
// ---------------------------------------------------------------------------
#define KC     32
#define RSTR   80
#define A_PL   (128 * RSTR)             // 10240
#define B_PL   (128 * RSTR)             // 10240
#define STG    (2 * A_PL + B_PL)        // 30720 per stage (A hi+lo, B hi)
#define SMEM_DYN (2 * STG)              // 61440 per CTA (x2 CTAs = 123KB/SM)

template<int KTOT, int NTOT, bool GELU>
__global__ void __launch_bounds__(256, 2) gemm_mma(
    const __half* __restrict__ Ah, const __half* __restrict__ Al,
    const __half* __restrict__ Bh,
    const float* __restrict__ bias,
    const float* __restrict__ xres, float* __restrict__ outp,
    __half* __restrict__ outH, __half* __restrict__ outL)
{
    constexpr int NS = KTOT / KC;
    extern __shared__ char smem[];
    const uint32_t sbase = smem_u32(smem);
    const int tid = threadIdx.x;
    const int lane = tid & 31;
    const int wrp = tid >> 5;
    const int wm = wrp & 3;          // M warp (32 rows)
    const int wn = wrp >> 2;         // N warp (64 cols), 0..1

    // block mapping: groups of 8 N-tiles x all 64 view-sorted M-tiles
    const int bx = blockIdx.x;
    const int g = bx >> 9, r = bx & 511;
    const int mb = g_morder[r >> 3];
    const int nb = (g << 3) | (r & 7);
    const int view = g_idx[mb >> 1];
    const int grow = mb * 128;
    const size_t arow0 = (size_t)grow;
    const size_t brow0 = (size_t)view * NTOT + (size_t)nb * 128;
    const int gcol = nb * 128;

    const char* pAh = (const char*)Ah;
    const char* pAl = (const char*)Al;
    const char* pBh = (const char*)Bh;

    auto load_stage = [&](int s) {
        const int k0 = s * KC;
        const uint32_t stb = sbase + (s & 1) * STG;
        #pragma unroll
        for (int i = 0; i < 2; i++) {
            int cid = i * 256 + tid;              // 512 = 128 rows x 4 chunks
            int row = cid >> 2, c = cid & 3;
            uint32_t so = stb + row * RSTR + c * 16;
            size_t go = ((size_t)(arow0 + row) * KTOT + k0 + c * 8) * 2;
            cp16(so, pAh + go);
            cp16(so + A_PL, pAl + go);
        }
        #pragma unroll
        for (int i = 0; i < 2; i++) {
            int cid = i * 256 + tid;
            int row = cid >> 2, c = cid & 3;
            uint32_t so = stb + 2 * A_PL + row * RSTR + c * 16;
            size_t go = ((size_t)(brow0 + row) * KTOT + k0 + c * 8) * 2;
            cp16(so, pBh + go);
        }
        CP_COMMIT();
    };

    const int lrow = (lane & 7) | (((lane >> 3) & 1) << 3);
    const int lhalf = lane >> 4;

    float    acc [2][8][4];
    uint32_t accX[2][8][2];
    #pragma unroll
    for (int i = 0; i < 2; i++)
        #pragma unroll
        for (int j = 0; j < 8; j++) {
            #pragma unroll
            for (int q = 0; q < 4; q++) acc[i][j][q] = 0.f;
            accX[i][j][0] = 0u; accX[i][j][1] = 0u;
        }

    load_stage(0);

    for (int s = 0; s < NS; s++) {
        CP_WAIT(0);
        __syncthreads();
        if (s + 1 < NS) load_stage(s + 1);

        const uint32_t stb = sbase + (s & 1) * STG;
        uint32_t aA = stb + (wm * 32 + lrow) * RSTR + lhalf * 16;
        uint32_t aB0 = stb + 2 * A_PL + (wn * 64 + lrow) * RSTR + lhalf * 16;

        #pragma unroll
        for (int kk = 0; kk < 2; kk++) {
            uint32_t ah[2][4], al[2][4];
            ldm4(ah[0], aA);
            ldm4(ah[1], aA + 16 * RSTR);
            ldm4(al[0], aA + A_PL);
            ldm4(al[1], aA + A_PL + 16 * RSTR);
            aA += 32;

            uint32_t aB = aB0;
            #pragma unroll
            for (int j16 = 0; j16 < 4; j16++) {
                uint32_t th[4];
                ldm4(th, aB);
                aB += 16 * RSTR;

                const int j0 = 2 * j16, j1 = j0 + 1;
                // main term (fp32 acc), 4 independent
                mma_f32(acc[0][j0], ah[0], th[0], th[2]);
                mma_f32(acc[1][j0], ah[1], th[0], th[2]);
                mma_f32(acc[0][j1], ah[0], th[1], th[3]);
                mma_f32(acc[1][j1], ah[1], th[1], th[3]);
                // cross term A-lo x B-hi (fp16 acc), 4 independent
                mma_f16(accX[0][j0], al[0], th[0], th[2]);
                mma_f16(accX[1][j0], al[1], th[0], th[2]);
                mma_f16(accX[0][j1], al[0], th[1], th[3]);
                mma_f16(accX[1][j1], al[1], th[1], th[3]);
            }
            aB0 += 32;
        }
    }

    // ---- epilogue ----
    const float* bias_v = bias + (size_t)view * NTOT;
    const int g4 = lane >> 2, t4 = lane & 3;

    #pragma unroll
    for (int i = 0; i < 2; i++) {
        #pragma unroll
        for (int j = 0; j < 8; j++) {
            const int row0 = grow + wm * 32 + i * 16 + g4;
            const int col  = gcol + wn * 64 + j * 8 + t4 * 2;
            const float b0 = __ldg(bias_v + col);
            const float b1 = __ldg(bias_v + col + 1);
            #pragma unroll
            for (int h = 0; h < 2; h++) {
                const int rw = row0 + h * 8;
                float2 xc = __half22float2(
                    *reinterpret_cast<const __half2*>(&accX[i][j][h]));
                float v0 = acc[i][j][h * 2 + 0] + xc.x + b0;
                float v1 = acc[i][j][h * 2 + 1] + xc.y + b1;
                const size_t go = (size_t)rw * NTOT + col;
                if (GELU) {
                    v0 = 0.5f * v0 * (1.0f + erff(v0 * 0.70710678118654752f));
                    v1 = 0.5f * v1 * (1.0f + erff(v1 * 0.70710678118654752f));
                    __half h0 = __float2half_rn(v0);
                    __half h1 = __float2half_rn(v1);
                    __half l0 = __float2half_rn(v0 - __half2float(h0));
                    __half l1 = __float2half_rn(v1 - __half2float(h1));
                    *(__half2*)(outH + go) = __halves2half2(h0, h1);
                    *(__half2*)(outL + go) = __halves2half2(l0, l1);
                } else {
                    float2 xv = *(const float2*)(xres + go);
                    float2 o;
                    o.x = xv.x + v0;
                    o.y = xv.y + v1;
                    *(float2*)(outp + go) = o;
                }
            }
        }
    }
}

// ---------------------------------------------------------------------------
// Launch
// ---------------------------------------------------------------------------
extern "C" void kernel_launch(void* const* d_in, const int* in_sizes, int n_in,
                              void* d_out, int out_size) {
    const float* x     = (const float*)d_in[0];
    const int*   idx   = (const int*)  d_in[1];
    const float* gamma = (const float*)d_in[2];
    const float* beta  = (const float*)d_in[3];
    const float* W1    = (const float*)d_in[4];
    const float* b1    = (const float*)d_in[5];
    const float* W2    = (const float*)d_in[6];
    const float* b2    = (const float*)d_in[7];
    float* out = (float*)d_out;

    void *p_xah, *p_xal, *p_hh, *p_hl, *p_w1h, *p_w2h;
    cudaGetSymbolAddress(&p_xah, g_xah);
    cudaGetSymbolAddress(&p_xal, g_xal);
    cudaGetSymbolAddress(&p_hh,  g_hh);
    cudaGetSymbolAddress(&p_hl,  g_hl);
    cudaGetSymbolAddress(&p_w1h, g_w1h);
    cudaGetSymbolAddress(&p_w2h, g_w2h);

    cudaFuncSetAttribute(gemm_mma<DIM, HID, true>,
                         cudaFuncAttributeMaxDynamicSharedMemorySize, SMEM_DYN);
    cudaFuncSetAttribute(gemm_mma<HID, DIM, false>,
                         cudaFuncAttributeMaxDynamicSharedMemorySize, SMEM_DYN);

    decode_idx_kernel<<<1, 1>>>(idx);
    ln_kernel<<<ROWS, 256>>>(x, gamma, beta);
    // W1: (2048/32)*(8192/64)=8192 blocks; W2: (8192/32)*(2048/64)=8192
    wt_all_kernel<<<dim3(8192, 6), 256>>>(W1, W2);

    // GEMM1: h = GELU(xn @ W1 + b1)   [8192x2048]x[2048x8192]
    gemm_mma<DIM, HID, true><<<(ROWS / 128) * (HID / 128), 256, SMEM_DYN>>>(
        (const __half*)p_xah, (const __half*)p_xal,
        (const __half*)p_w1h,
        b1, nullptr, nullptr,
        (__half*)p_hh, (__half*)p_hl);

    // GEMM2: out = x + h @ W2 + b2    [8192x8192]x[8192x2048]
    gemm_mma<HID, DIM, false><<<(ROWS / 128) * (DIM / 128), 256, SMEM_DYN>>>(
        (const __half*)p_hh, (const __half*)p_hl,
        (const __half*)p_w2h,
        b2, x, out, nullptr, nullptr);
}

// round 16
// speedup vs baseline: 2.4282x; 1.8537x over previous
#include <cuda_runtime.h>
#include <cuda_fp16.h>
#include <math.h>
#include <stdint.h>

// Problem dims
#define BATCH 32
#define PTOK  256
#define DIM   2048
#define HID   8192
#define NVIEW 3
#define ROWS  (BATCH * PTOK)   // 8192

// ---------------------------------------------------------------------------
// Device scratch
// ---------------------------------------------------------------------------
__device__ int g_idx[BATCH];
__device__ int g_morder[ROWS / 128];

__device__ __half g_xa [(size_t)ROWS * DIM];         // LN output, fp16
__device__ __half g_h  [(size_t)ROWS * HID];         // GELU output, fp16
__device__ __half g_w1h[(size_t)NVIEW * HID * DIM];  // [v][n][k] fp16
__device__ __half g_w2h[(size_t)NVIEW * DIM * HID];

// ---------------------------------------------------------------------------
// PTX helpers (base sm_103-safe)
// ---------------------------------------------------------------------------
__device__ __forceinline__ uint32_t smem_u32(const void* p) {
    uint32_t a;
    asm("{ .reg .u64 t; cvta.to.shared.u64 t, %1; cvt.u32.u64 %0, t; }"
        : "=r"(a) : "l"(p));
    return a;
}

__device__ __forceinline__ void cp16(uint32_t dst, const void* src) {
    asm volatile("cp.async.cg.shared.global [%0], [%1], 16;" :: "r"(dst), "l"(src));
}
#define CP_COMMIT() asm volatile("cp.async.commit_group;" ::: "memory")
#define CP_WAIT(n)  asm volatile("cp.async.wait_group %0;" :: "n"(n) : "memory")

__device__ __forceinline__ void ldm4(uint32_t* r, uint32_t a) {
    asm volatile("ldmatrix.sync.aligned.m8n8.x4.shared.b16 {%0,%1,%2,%3}, [%4];"
        : "=r"(r[0]), "=r"(r[1]), "=r"(r[2]), "=r"(r[3]) : "r"(a));
}

// fp16 inputs, fp32 accumulator
__device__ __forceinline__ void mma_f32(float* c, const uint32_t* a,
                                        uint32_t b0, uint32_t b1) {
    asm volatile(
        "mma.sync.aligned.m16n8k16.row.col.f32.f16.f16.f32 "
        "{%0,%1,%2,%3}, {%4,%5,%6,%7}, {%8,%9}, {%0,%1,%2,%3};"
        : "+f"(c[0]), "+f"(c[1]), "+f"(c[2]), "+f"(c[3])
        : "r"(a[0]), "r"(a[1]), "r"(a[2]), "r"(a[3]), "r"(b0), "r"(b1));
}

// ---------------------------------------------------------------------------
// decode idx + view-sorted M-tile order (128-row tiles: 2 per sample)
// ---------------------------------------------------------------------------
__global__ void decode_idx_kernel(const int* __restrict__ p) {
    bool is64 = true;
    for (int b = 0; b < BATCH; b++) {
        int lo = p[2 * b], hi = p[2 * b + 1];
        if (!(lo >= 0 && lo < NVIEW && hi == 0)) { is64 = false; break; }
    }
    for (int b = 0; b < BATCH; b++) g_idx[b] = is64 ? p[2 * b] : p[b];
    int c = 0;
    for (int v = 0; v < NVIEW; v++)
        for (int s = 0; s < BATCH; s++)
            if (g_idx[s] == v) { g_morder[c++] = 2 * s; g_morder[c++] = 2 * s + 1; }
}

// ---------------------------------------------------------------------------
// LayerNorm -> fp16
// ---------------------------------------------------------------------------
__global__ void __launch_bounds__(256) ln_kernel(
    const float* __restrict__ x,
    const float* __restrict__ gamma,
    const float* __restrict__ beta)
{
    const int row = blockIdx.x;
    const int view = g_idx[row >> 8];
    const float* xr = x + (size_t)row * DIM;
    const int tid = threadIdx.x;

    float4 v0 = *(const float4*)(xr + tid * 4);
    float4 v1 = *(const float4*)(xr + 1024 + tid * 4);

    float s  = v0.x + v0.y + v0.z + v0.w + v1.x + v1.y + v1.z + v1.w;
    float ss = v0.x*v0.x + v0.y*v0.y + v0.z*v0.z + v0.w*v0.w
             + v1.x*v1.x + v1.y*v1.y + v1.z*v1.z + v1.w*v1.w;
    #pragma unroll
    for (int off = 16; off > 0; off >>= 1) {
        s  += __shfl_xor_sync(0xffffffffu, s,  off);
        ss += __shfl_xor_sync(0xffffffffu, ss, off);
    }
    __shared__ float rs[8], rss[8];
    int wid = tid >> 5, lane = tid & 31;
    if (lane == 0) { rs[wid] = s; rss[wid] = ss; }
    __syncthreads();
    if (wid == 0) {
        float a = (lane < 8) ? rs[lane] : 0.f;
        float b = (lane < 8) ? rss[lane] : 0.f;
        #pragma unroll
        for (int off = 4; off > 0; off >>= 1) {
            a += __shfl_xor_sync(0xffffffffu, a, off);
            b += __shfl_xor_sync(0xffffffffu, b, off);
        }
        if (lane == 0) { rs[0] = a; rss[0] = b; }
    }
    __syncthreads();
    const float mean = rs[0] * (1.0f / DIM);
    const float var  = rss[0] * (1.0f / DIM) - mean * mean;
    const float inv  = rsqrtf(var + 1e-5f);

    const float* g = gamma + (size_t)view * DIM;
    const float* b = beta  + (size_t)view * DIM;
    size_t base = (size_t)row * DIM;

    float v[8];
    v[0]=v0.x; v[1]=v0.y; v[2]=v0.z; v[3]=v0.w; v[4]=v1.x; v[5]=v1.y; v[6]=v1.z; v[7]=v1.w;
    #pragma unroll
    for (int j = 0; j < 8; j++) {
        int c = (j < 4) ? (tid * 4 + j) : (1024 + tid * 4 + (j - 4));
        float o = (v[j] - mean) * inv * g[c] + b[c];
        g_xa[base + c] = __float2half_rn(o);
    }
}

// ---------------------------------------------------------------------------
// Fused weight transpose + fp16: 32k x 64n tiles.
// blockIdx.y in [0,6): y<3 -> W1 view y ; y>=3 -> W2 view y-3
// ---------------------------------------------------------------------------
__global__ void __launch_bounds__(256) wt_all_kernel(
    const float* __restrict__ W1, const float* __restrict__ W2)
{
    __shared__ float t[32][65];
    const int yy = blockIdx.y;
    const bool isW1 = (yy < 3);
    const int v = isW1 ? yy : (yy - 3);
    const int K = isW1 ? DIM : HID;
    const int N = isW1 ? HID : DIM;
    const float* W = isW1 ? W1 : W2;
    __half* oh = isW1 ? g_w1h : g_w2h;

    const int nblk = N / 64;
    const int kb = blockIdx.x / nblk;
    const int nb = blockIdx.x % nblk;
    const int n0 = nb * 64, k0 = kb * 32;
    const int tid = threadIdx.x;

    #pragma unroll
    for (int i = 0; i < 2; i++) {
        int cid = i * 256 + tid;             // 512 float4 = 32 rows x 16
        int row = cid >> 4, c4 = cid & 15;
        float4 val = *(const float4*)(W + ((size_t)v * K + k0 + row) * N + n0 + c4 * 4);
        t[row][c4 * 4 + 0] = val.x;
        t[row][c4 * 4 + 1] = val.y;
        t[row][c4 * 4 + 2] = val.z;
        t[row][c4 * 4 + 3] = val.w;
    }
    __syncthreads();

    const int n = tid >> 2;                  // 0..63
    const int kq = (tid & 3) * 8;            // 0,8,16,24
    __half hs[8];
    #pragma unroll
    for (int i = 0; i < 8; i++)
        hs[i] = __float2half_rn(t[kq + i][n]);
    size_t o = ((size_t)v * N + n0 + n) * K + k0 + kq;
    *(uint4*)(oh + o) = *(const uint4*)hs;
}

// ---------------------------------------------------------------------------
// Warp-MMA GEMM: D[128x128] = A[128xK] @ B[128xK]^T, pure fp16 operands,
// fp32 accumulators. 256 threads = 8 warps (4M x 2N), warp tile 32x64.
// 2 CTAs/SM. K-chunk 32, 3-stage cp.async ring (loads 2 stages ahead).
// ---------------------------------------------------------------------------
#define KC     32
#define RSTR   80
#define A_PL   (128 * RSTR)             // 10240
#define B_PL   (128 * RSTR)             // 10240
#define STG    (A_PL + B_PL)            // 20480 per stage
#define NSTAGE 3
#define SMEM_DYN (NSTAGE * STG)         // 61440 per CTA (x2 CTAs = 123KB/SM)

template<int KTOT, int NTOT, bool GELU>
__global__ void __launch_bounds__(256, 2) gemm_mma(
    const __half* __restrict__ Ah,
    const __half* __restrict__ Bh,
    const float* __restrict__ bias,
    const float* __restrict__ xres, float* __restrict__ outp,
    __half* __restrict__ outH)
{
    constexpr int NS = KTOT / KC;
    extern __shared__ char smem[];
    const uint32_t sbase = smem_u32(smem);
    const int tid = threadIdx.x;
    const int lane = tid & 31;
    const int wrp = tid >> 5;
    const int wm = wrp & 3;          // M warp (32 rows)
    const int wn = wrp >> 2;         // N warp (64 cols), 0..1

    // block mapping: groups of 8 N-tiles x all 64 view-sorted M-tiles
    const int bx = blockIdx.x;
    const int g = bx >> 9, r = bx & 511;
    const int mb = g_morder[r >> 3];
    const int nb = (g << 3) | (r & 7);
    const int view = g_idx[mb >> 1];
    const int grow = mb * 128;
    const size_t arow0 = (size_t)grow;
    const size_t brow0 = (size_t)view * NTOT + (size_t)nb * 128;
    const int gcol = nb * 128;

    const char* pAh = (const char*)Ah;
    const char* pBh = (const char*)Bh;

    auto load_stage = [&](int s) {
        const int k0 = s * KC;
        const uint32_t stb = sbase + (s % NSTAGE) * STG;
        #pragma unroll
        for (int i = 0; i < 2; i++) {
            int cid = i * 256 + tid;              // 512 = 128 rows x 4 chunks
            int row = cid >> 2, c = cid & 3;
            uint32_t so = stb + row * RSTR + c * 16;
            size_t go = ((size_t)(arow0 + row) * KTOT + k0 + c * 8) * 2;
            cp16(so, pAh + go);
        }
        #pragma unroll
        for (int i = 0; i < 2; i++) {
            int cid = i * 256 + tid;
            int row = cid >> 2, c = cid & 3;
            uint32_t so = stb + A_PL + row * RSTR + c * 16;
            size_t go = ((size_t)(brow0 + row) * KTOT + k0 + c * 8) * 2;
            cp16(so, pBh + go);
        }
        CP_COMMIT();
    };

    const int lrow = (lane & 7) | (((lane >> 3) & 1) << 3);
    const int lhalf = lane >> 4;

    float acc[2][8][4];
    #pragma unroll
    for (int i = 0; i < 2; i++)
        #pragma unroll
        for (int j = 0; j < 8; j++)
            #pragma unroll
            for (int q = 0; q < 4; q++) acc[i][j][q] = 0.f;

    load_stage(0);
    load_stage(1);

    for (int s = 0; s < NS; s++) {
        if (s + 1 < NS) { CP_WAIT(1); }
        else            { CP_WAIT(0); }
        __syncthreads();
        if (s + 2 < NS) load_stage(s + 2);

        const uint32_t stb = sbase + (s % NSTAGE) * STG;
        uint32_t aA = stb + (wm * 32 + lrow) * RSTR + lhalf * 16;
        uint32_t aB0 = stb + A_PL + (wn * 64 + lrow) * RSTR + lhalf * 16;

        #pragma unroll
        for (int kk = 0; kk < 2; kk++) {
            uint32_t ah[2][4];
            ldm4(ah[0], aA);
            ldm4(ah[1], aA + 16 * RSTR);
            aA += 32;

            uint32_t aB = aB0;
            #pragma unroll
            for (int j16 = 0; j16 < 4; j16++) {
                uint32_t th[4];
                ldm4(th, aB);
                aB += 16 * RSTR;

                const int j0 = 2 * j16, j1 = j0 + 1;
                // 4 independent MMAs (acc RAW spacing 4)
                mma_f32(acc[0][j0], ah[0], th[0], th[2]);
                mma_f32(acc[1][j0], ah[1], th[0], th[2]);
                mma_f32(acc[0][j1], ah[0], th[1], th[3]);
                mma_f32(acc[1][j1], ah[1], th[1], th[3]);
            }
            aB0 += 32;
        }
    }

    // ---- epilogue ----
    const float* bias_v = bias + (size_t)view * NTOT;
    const int g4 = lane >> 2, t4 = lane & 3;

    #pragma unroll
    for (int i = 0; i < 2; i++) {
        #pragma unroll
        for (int j = 0; j < 8; j++) {
            const int row0 = grow + wm * 32 + i * 16 + g4;
            const int col  = gcol + wn * 64 + j * 8 + t4 * 2;
            const float b0 = __ldg(bias_v + col);
            const float b1 = __ldg(bias_v + col + 1);
            #pragma unroll
            for (int h = 0; h < 2; h++) {
                const int rw = row0 + h * 8;
                float v0 = acc[i][j][h * 2 + 0] + b0;
                float v1 = acc[i][j][h * 2 + 1] + b1;
                const size_t go = (size_t)rw * NTOT + col;
                if (GELU) {
                    v0 = 0.5f * v0 * (1.0f + erff(v0 * 0.70710678118654752f));
                    v1 = 0.5f * v1 * (1.0f + erff(v1 * 0.70710678118654752f));
                    *(__half2*)(outH + go) =
                        __halves2half2(__float2half_rn(v0), __float2half_rn(v1));
                } else {
                    float2 xv = *(const float2*)(xres + go);
                    float2 o;
                    o.x = xv.x + v0;
                    o.y = xv.y + v1;
                    *(float2*)(outp + go) = o;
                }
            }
        }
    }
}

// ---------------------------------------------------------------------------
// Launch
// ---------------------------------------------------------------------------
extern "C" void kernel_launch(void* const* d_in, const int* in_sizes, int n_in,
                              void* d_out, int out_size) {
    const float* x     = (const float*)d_in[0];
    const int*   idx   = (const int*)  d_in[1];
    const float* gamma = (const float*)d_in[2];
    const float* beta  = (const float*)d_in[3];
    const float* W1    = (const float*)d_in[4];
    const float* b1    = (const float*)d_in[5];
    const float* W2    = (const float*)d_in[6];
    const float* b2    = (const float*)d_in[7];
    float* out = (float*)d_out;

    void *p_xa, *p_h, *p_w1h, *p_w2h;
    cudaGetSymbolAddress(&p_xa,  g_xa);
    cudaGetSymbolAddress(&p_h,   g_h);
    cudaGetSymbolAddress(&p_w1h, g_w1h);
    cudaGetSymbolAddress(&p_w2h, g_w2h);

    cudaFuncSetAttribute(gemm_mma<DIM, HID, true>,
                         cudaFuncAttributeMaxDynamicSharedMemorySize, SMEM_DYN);
    cudaFuncSetAttribute(gemm_mma<HID, DIM, false>,
                         cudaFuncAttributeMaxDynamicSharedMemorySize, SMEM_DYN);

    decode_idx_kernel<<<1, 1>>>(idx);
    ln_kernel<<<ROWS, 256>>>(x, gamma, beta);
    // W1: (2048/32)*(8192/64)=8192 blocks; W2: (8192/32)*(2048/64)=8192
    wt_all_kernel<<<dim3(8192, 6), 256>>>(W1, W2);

    // GEMM1: h = GELU(xn @ W1 + b1)   [8192x2048]x[2048x8192]
    gemm_mma<DIM, HID, true><<<(ROWS / 128) * (HID / 128), 256, SMEM_DYN>>>(
        (const __half*)p_xa,
        (const __half*)p_w1h,
        b1, nullptr, nullptr,
        (__half*)p_h);

    // GEMM2: out = x + h @ W2 + b2    [8192x8192]x[8192x2048]
    gemm_mma<HID, DIM, false><<<(ROWS / 128) * (DIM / 128), 256, SMEM_DYN>>>(
        (const __half*)p_h,
        (const __half*)p_w2h,
        b2, x, out, nullptr);
}

// round 17
// speedup vs baseline: 2.7323x; 1.1253x over previous
#include <cuda_runtime.h>
#include <cuda_fp16.h>
#include <math.h>
#include <stdint.h>

// Problem dims
#define BATCH 32
#define PTOK  256
#define DIM   2048
#define HID   8192
#define NVIEW 3
#define ROWS  (BATCH * PTOK)   // 8192

// ---------------------------------------------------------------------------
// Device scratch
// ---------------------------------------------------------------------------
__device__ int g_idx[BATCH];
__device__ int g_morder[ROWS / 128];

__device__ __half g_xa [(size_t)ROWS * DIM];         // LN output, fp16
__device__ __half g_h  [(size_t)ROWS * HID];         // GELU output, fp16
__device__ __half g_w1h[(size_t)NVIEW * HID * DIM];  // [v][n][k] fp16
__device__ __half g_w2h[(size_t)NVIEW * DIM * HID];

// ---------------------------------------------------------------------------
// PTX helpers (base sm_103-safe)
// ---------------------------------------------------------------------------
__device__ __forceinline__ uint32_t smem_u32(const void* p) {
    uint32_t a;
    asm("{ .reg .u64 t; cvta.to.shared.u64 t, %1; cvt.u32.u64 %0, t; }"
        : "=r"(a) : "l"(p));
    return a;
}

__device__ __forceinline__ void cp16(uint32_t dst, const void* src) {
    asm volatile("cp.async.cg.shared.global [%0], [%1], 16;" :: "r"(dst), "l"(src));
}
#define CP_COMMIT() asm volatile("cp.async.commit_group;" ::: "memory")
#define CP_WAIT(n)  asm volatile("cp.async.wait_group %0;" :: "n"(n) : "memory")

__device__ __forceinline__ void ldm4(uint32_t* r, uint32_t a) {
    asm volatile("ldmatrix.sync.aligned.m8n8.x4.shared.b16 {%0,%1,%2,%3}, [%4];"
        : "=r"(r[0]), "=r"(r[1]), "=r"(r[2]), "=r"(r[3]) : "r"(a));
}

// fp16 inputs, fp32 accumulator
__device__ __forceinline__ void mma_f32(float* c, const uint32_t* a,
                                        uint32_t b0, uint32_t b1) {
    asm volatile(
        "mma.sync.aligned.m16n8k16.row.col.f32.f16.f16.f32 "
        "{%0,%1,%2,%3}, {%4,%5,%6,%7}, {%8,%9}, {%0,%1,%2,%3};"
        : "+f"(c[0]), "+f"(c[1]), "+f"(c[2]), "+f"(c[3])
        : "r"(a[0]), "r"(a[1]), "r"(a[2]), "r"(a[3]), "r"(b0), "r"(b1));
}

// ---------------------------------------------------------------------------
// decode idx + view-sorted M-tile order (128-row tiles: 2 per sample)
// ---------------------------------------------------------------------------
__global__ void decode_idx_kernel(const int* __restrict__ p) {
    bool is64 = true;
    for (int b = 0; b < BATCH; b++) {
        int lo = p[2 * b], hi = p[2 * b + 1];
        if (!(lo >= 0 && lo < NVIEW && hi == 0)) { is64 = false; break; }
    }
    for (int b = 0; b < BATCH; b++) g_idx[b] = is64 ? p[2 * b] : p[b];
    int c = 0;
    for (int v = 0; v < NVIEW; v++)
        for (int s = 0; s < BATCH; s++)
            if (g_idx[s] == v) { g_morder[c++] = 2 * s; g_morder[c++] = 2 * s + 1; }
}

// ---------------------------------------------------------------------------
// LayerNorm -> fp16
// ---------------------------------------------------------------------------
__global__ void __launch_bounds__(256) ln_kernel(
    const float* __restrict__ x,
    const float* __restrict__ gamma,
    const float* __restrict__ beta)
{
    const int row = blockIdx.x;
    const int view = g_idx[row >> 8];
    const float* xr = x + (size_t)row * DIM;
    const int tid = threadIdx.x;

    float4 v0 = *(const float4*)(xr + tid * 4);
    float4 v1 = *(const float4*)(xr + 1024 + tid * 4);

    float s  = v0.x + v0.y + v0.z + v0.w + v1.x + v1.y + v1.z + v1.w;
    float ss = v0.x*v0.x + v0.y*v0.y + v0.z*v0.z + v0.w*v0.w
             + v1.x*v1.x + v1.y*v1.y + v1.z*v1.z + v1.w*v1.w;
    #pragma unroll
    for (int off = 16; off > 0; off >>= 1) {
        s  += __shfl_xor_sync(0xffffffffu, s,  off);
        ss += __shfl_xor_sync(0xffffffffu, ss, off);
    }
    __shared__ float rs[8], rss[8];
    int wid = tid >> 5, lane = tid & 31;
    if (lane == 0) { rs[wid] = s; rss[wid] = ss; }
    __syncthreads();
    if (wid == 0) {
        float a = (lane < 8) ? rs[lane] : 0.f;
        float b = (lane < 8) ? rss[lane] : 0.f;
        #pragma unroll
        for (int off = 4; off > 0; off >>= 1) {
            a += __shfl_xor_sync(0xffffffffu, a, off);
            b += __shfl_xor_sync(0xffffffffu, b, off);
        }
        if (lane == 0) { rs[0] = a; rss[0] = b; }
    }
    __syncthreads();
    const float mean = rs[0] * (1.0f / DIM);
    const float var  = rss[0] * (1.0f / DIM) - mean * mean;
    const float inv  = rsqrtf(var + 1e-5f);

    const float* g = gamma + (size_t)view * DIM;
    const float* b = beta  + (size_t)view * DIM;
    size_t base = (size_t)row * DIM;

    float v[8];
    v[0]=v0.x; v[1]=v0.y; v[2]=v0.z; v[3]=v0.w; v[4]=v1.x; v[5]=v1.y; v[6]=v1.z; v[7]=v1.w;
    #pragma unroll
    for (int j = 0; j < 8; j++) {
        int c = (j < 4) ? (tid * 4 + j) : (1024 + tid * 4 + (j - 4));
        float o = (v[j] - mean) * inv * g[c] + b[c];
        g_xa[base + c] = __float2half_rn(o);
    }
}

// ---------------------------------------------------------------------------
// Fused weight transpose + fp16: 32k x 64n tiles.
// blockIdx.y in [0,6): y<3 -> W1 view y ; y>=3 -> W2 view y-3
// ---------------------------------------------------------------------------
__global__ void __launch_bounds__(256) wt_all_kernel(
    const float* __restrict__ W1, const float* __restrict__ W2)
{
    __shared__ float t[32][65];
    const int yy = blockIdx.y;
    const bool isW1 = (yy < 3);
    const int v = isW1 ? yy : (yy - 3);
    const int K = isW1 ? DIM : HID;
    const int N = isW1 ? HID : DIM;
    const float* W = isW1 ? W1 : W2;
    __half* oh = isW1 ? g_w1h : g_w2h;

    const int nblk = N / 64;
    const int kb = blockIdx.x / nblk;
    const int nb = blockIdx.x % nblk;
    const int n0 = nb * 64, k0 = kb * 32;
    const int tid = threadIdx.x;

    #pragma unroll
    for (int i = 0; i < 2; i++) {
        int cid = i * 256 + tid;             // 512 float4 = 32 rows x 16
        int row = cid >> 4, c4 = cid & 15;
        float4 val = *(const float4*)(W + ((size_t)v * K + k0 + row) * N + n0 + c4 * 4);
        t[row][c4 * 4 + 0] = val.x;
        t[row][c4 * 4 + 1] = val.y;
        t[row][c4 * 4 + 2] = val.z;
        t[row][c4 * 4 + 3] = val.w;
    }
    __syncthreads();

    const int n = tid >> 2;                  // 0..63
    const int kq = (tid & 3) * 8;            // 0,8,16,24
    __half hs[8];
    #pragma unroll
    for (int i = 0; i < 8; i++)
        hs[i] = __float2half_rn(t[kq + i][n]);
    size_t o = ((size_t)v * N + n0 + n) * K + k0 + kq;
    *(uint4*)(oh + o) = *(const uint4*)hs;
}

// ---------------------------------------------------------------------------
// Warp-MMA GEMM: D[128x128] = A[128xK] @ B[128xK]^T, pure fp16 operands,
// fp32 accumulators. 256 threads = 8 warps (4M x 2N), warp tile 32x64.
// 2 CTAs/SM. K-chunk 64, 3-stage cp.async ring (loads 2 stages ahead).
// B fragments double-buffered (prefetch j16+1 during j16's MMAs).
// ---------------------------------------------------------------------------
#define KC     64
#define RSTR   144                      // 64 fp16 = 128B + 16B pad
#define A_PL   (128 * RSTR)             // 18432
#define B_PL   (128 * RSTR)             // 18432
#define STG    (A_PL + B_PL)            // 36864 per stage
#define NSTAGE 3
#define SMEM_DYN (NSTAGE * STG)         // 110592 per CTA (x2 CTAs = 221KB/SM)

template<int KTOT, int NTOT, bool GELU>
__global__ void __launch_bounds__(256, 2) gemm_mma(
    const __half* __restrict__ Ah,
    const __half* __restrict__ Bh,
    const float* __restrict__ bias,
    const float* __restrict__ xres, float* __restrict__ outp,
    __half* __restrict__ outH)
{
    constexpr int NS = KTOT / KC;
    extern __shared__ char smem[];
    const uint32_t sbase = smem_u32(smem);
    const int tid = threadIdx.x;
    const int lane = tid & 31;
    const int wrp = tid >> 5;
    const int wm = wrp & 3;          // M warp (32 rows)
    const int wn = wrp >> 2;         // N warp (64 cols), 0..1

    // block mapping: groups of 8 N-tiles x all 64 view-sorted M-tiles
    const int bx = blockIdx.x;
    const int g = bx >> 9, r = bx & 511;
    const int mb = g_morder[r >> 3];
    const int nb = (g << 3) | (r & 7);
    const int view = g_idx[mb >> 1];
    const int grow = mb * 128;
    const size_t arow0 = (size_t)grow;
    const size_t brow0 = (size_t)view * NTOT + (size_t)nb * 128;
    const int gcol = nb * 128;

    const char* pAh = (const char*)Ah;
    const char* pBh = (const char*)Bh;

    // stage loader: A/B 128 rows x 64 k fp16 (4 cp16/thread each)
    auto load_stage = [&](int s) {
        const int k0 = s * KC;
        const uint32_t stb = sbase + (s % NSTAGE) * STG;
        #pragma unroll
        for (int i = 0; i < 4; i++) {
            int cid = i * 256 + tid;              // 1024 = 128 rows x 8 chunks
            int row = cid >> 3, c = cid & 7;
            uint32_t so = stb + row * RSTR + c * 16;
            size_t go = ((size_t)(arow0 + row) * KTOT + k0 + c * 8) * 2;
            cp16(so, pAh + go);
        }
        #pragma unroll
        for (int i = 0; i < 4; i++) {
            int cid = i * 256 + tid;
            int row = cid >> 3, c = cid & 7;
            uint32_t so = stb + A_PL + row * RSTR + c * 16;
            size_t go = ((size_t)(brow0 + row) * KTOT + k0 + c * 8) * 2;
            cp16(so, pBh + go);
        }
        CP_COMMIT();
    };

    const int lrow = (lane & 7) | (((lane >> 3) & 1) << 3);
    const int lhalf = lane >> 4;

    float acc[2][8][4];
    #pragma unroll
    for (int i = 0; i < 2; i++)
        #pragma unroll
        for (int j = 0; j < 8; j++)
            #pragma unroll
            for (int q = 0; q < 4; q++) acc[i][j][q] = 0.f;

    load_stage(0);
    load_stage(1);

    for (int s = 0; s < NS; s++) {
        if (s + 1 < NS) { CP_WAIT(1); }
        else            { CP_WAIT(0); }
        __syncthreads();
        if (s + 2 < NS) load_stage(s + 2);

        const uint32_t stb = sbase + (s % NSTAGE) * STG;
        uint32_t aA = stb + (wm * 32 + lrow) * RSTR + lhalf * 16;
        uint32_t aB0 = stb + A_PL + (wn * 64 + lrow) * RSTR + lhalf * 16;

        #pragma unroll
        for (int kk = 0; kk < 4; kk++) {           // 4 x k16 per stage
            uint32_t ah[2][4];
            ldm4(ah[0], aA);
            ldm4(ah[1], aA + 16 * RSTR);
            aA += 32;

            uint32_t th[2][4];
            ldm4(th[0], aB0);                      // prefetch j16=0
            #pragma unroll
            for (int j16 = 0; j16 < 4; j16++) {
                const int cur = j16 & 1, nxt = cur ^ 1;
                if (j16 < 3)
                    ldm4(th[nxt], aB0 + (j16 + 1) * 16 * RSTR);

                const int j0 = 2 * j16, j1 = j0 + 1;
                mma_f32(acc[0][j0], ah[0], th[cur][0], th[cur][2]);
                mma_f32(acc[1][j0], ah[1], th[cur][0], th[cur][2]);
                mma_f32(acc[0][j1], ah[0], th[cur][1], th[cur][3]);
                mma_f32(acc[1][j1], ah[1], th[cur][1], th[cur][3]);
            }
            aB0 += 32;
        }
    }

    // ---- epilogue ----
    const float* bias_v = bias + (size_t)view * NTOT;
    const int g4 = lane >> 2, t4 = lane & 3;

    #pragma unroll
    for (int i = 0; i < 2; i++) {
        #pragma unroll
        for (int j = 0; j < 8; j++) {
            const int row0 = grow + wm * 32 + i * 16 + g4;
            const int col  = gcol + wn * 64 + j * 8 + t4 * 2;
            const float b0 = __ldg(bias_v + col);
            const float b1 = __ldg(bias_v + col + 1);
            #pragma unroll
            for (int h = 0; h < 2; h++) {
                const int rw = row0 + h * 8;
                float v0 = acc[i][j][h * 2 + 0] + b0;
                float v1 = acc[i][j][h * 2 + 1] + b1;
                const size_t go = (size_t)rw * NTOT + col;
                if (GELU) {
                    v0 = 0.5f * v0 * (1.0f + erff(v0 * 0.70710678118654752f));
                    v1 = 0.5f * v1 * (1.0f + erff(v1 * 0.70710678118654752f));
                    *(__half2*)(outH + go) =
                        __halves2half2(__float2half_rn(v0), __float2half_rn(v1));
                } else {
                    float2 xv = *(const float2*)(xres + go);
                    float2 o;
                    o.x = xv.x + v0;
                    o.y = xv.y + v1;
                    *(float2*)(outp + go) = o;
                }
            }
        }
    }
}

// ---------------------------------------------------------------------------
// Launch
// ---------------------------------------------------------------------------
extern "C" void kernel_launch(void* const* d_in, const int* in_sizes, int n_in,
                              void* d_out, int out_size) {
    const float* x     = (const float*)d_in[0];
    const int*   idx   = (const int*)  d_in[1];
    const float* gamma = (const float*)d_in[2];
    const float* beta  = (const float*)d_in[3];
    const float* W1    = (const float*)d_in[4];
    const float* b1    = (const float*)d_in[5];
    const float* W2    = (const float*)d_in[6];
    const float* b2    = (const float*)d_in[7];
    float* out = (float*)d_out;

    void *p_xa, *p_h, *p_w1h, *p_w2h;
    cudaGetSymbolAddress(&p_xa,  g_xa);
    cudaGetSymbolAddress(&p_h,   g_h);
    cudaGetSymbolAddress(&p_w1h, g_w1h);
    cudaGetSymbolAddress(&p_w2h, g_w2h);

    cudaFuncSetAttribute(gemm_mma<DIM, HID, true>,
                         cudaFuncAttributeMaxDynamicSharedMemorySize, SMEM_DYN);
    cudaFuncSetAttribute(gemm_mma<HID, DIM, false>,
                         cudaFuncAttributeMaxDynamicSharedMemorySize, SMEM_DYN);

    decode_idx_kernel<<<1, 1>>>(idx);
    ln_kernel<<<ROWS, 256>>>(x, gamma, beta);
    wt_all_kernel<<<dim3(8192, 6), 256>>>(W1, W2);

    // GEMM1: h = GELU(xn @ W1 + b1)   [8192x2048]x[2048x8192]
    gemm_mma<DIM, HID, true><<<(ROWS / 128) * (HID / 128), 256, SMEM_DYN>>>(
        (const __half*)p_xa,
        (const __half*)p_w1h,
        b1, nullptr, nullptr,
        (__half*)p_h);

    // GEMM2: out = x + h @ W2 + b2    [8192x8192]x[8192x2048]
    gemm_mma<HID, DIM, false><<<(ROWS / 128) * (DIM / 128), 256, SMEM_DYN>>>(
        (const __half*)p_h,
        (const __half*)p_w2h,
        b2, x, out, nullptr);
}